// round 14
// baseline (speedup 1.0000x reference)
#include <cuda_runtime.h>
#include <cstdint>

#define FULL 0xFFFFFFFFu

// Static scratch (no allocations):
__device__ float4   g_scal[32];              // per-b: {inv_r, Tp, Tn, flag}
__device__ float    g_comb[16 * 32 * 1024];  // [split][b][c] combined partials, 2MB
__device__ unsigned g_prep  = 0;             // prep-done counter (self-reset)
__device__ unsigned g_all   = 0;             // all-block arrivals (self-reset)
__device__ unsigned g_rdone = 0;             // reducers done (self-reset)

// Order-preserving float <-> uint mapping (monotone for non-NaN).
__device__ __forceinline__ unsigned f2ord(float f) {
    unsigned b = __float_as_uint(f);
    return (b & 0x80000000u) ? ~b : (b | 0x80000000u);
}
__device__ __forceinline__ float ord2f(unsigned u) {
    unsigned b = (u & 0x80000000u) ? (u ^ 0x80000000u) : ~u;
    return __uint_as_float(b);
}

// Packed fp32x2 FMA (Blackwell FFMA2).
__device__ __forceinline__ unsigned long long ffma2(
    unsigned long long a, unsigned long long b, unsigned long long c) {
    unsigned long long d;
    asm("fma.rn.f32x2 %0, %1, %2, %3;" : "=l"(d) : "l"(a), "l"(b), "l"(c));
    return d;
}

union SmemU {
    struct {
        unsigned hist[2048];
        unsigned candT[2048];
        unsigned candB[2048];
        float    red[16];
        unsigned mm[16];
        int      bnd[4];
        unsigned cnt[2];
        float    sum[16];
        float    scal[4];
    } p;
    struct {
        float Ws[64 * 64];      // [c][k] 16KB
        float FsP[32 * 68];     // max(rad,0), pitch 68
        float FsM[32 * 68];     // min(rad,0)
    } g;
    struct {
        float4 s_p[8][32];      // reduce tree (4KB)
    } r;
};

// ---------------------------------------------------------------------------
// Single kernel, grid = 288, __launch_bounds__(256, 2):
//   reg cap 128 (no spills, unlike R12's 84) and 148*2=296 >= 288 blocks
//   => ALL blocks co-resident => global barrier is deadlock-free.
//   blocks 0..31   : prep -> g_scal, publish g_prep, arrive g_all, exit
//   blocks 32..287 : GEMM (64c x 128k, 2 chunks) -> wait g_prep -> fold
//                    per-batch coefficients -> store combined 2MB -> arrive
//                    g_all -> spin to 288 -> reduce L2-hot -> out.
// ---------------------------------------------------------------------------
__global__ void __launch_bounds__(256, 2) fused_kernel(
    const float* __restrict__ f_rad,    // [32,1024]
    const float* __restrict__ f_histo,  // [32,2048]
    const int*   __restrict__ rad_mask, // [32]
    const int*   __restrict__ histo_mask,
    const float* __restrict__ W,        // [1024,2048]
    const float* __restrict__ bias,     // [1024]
    const float* __restrict__ token,    // [1024]
    float* __restrict__ out)            // [32,1024]
{
    __shared__ __align__(16) SmemU sm;

    const int tid  = threadIdx.x;
    const int lane = tid & 31;
    const int wid  = tid >> 5;

    if (blockIdx.x < 32) {
        // ======================= PREP (proven) =======================
        const int b = blockIdx.x;
        const float* rad = f_rad   + b * 1024;
        const float* his = f_histo + b * 2048;

        #pragma unroll
        for (int j = 0; j < 8; j++) sm.p.hist[tid + 256 * j] = 0;
        if (tid < 2) sm.p.cnt[tid] = 0;

        float sr = 0.f, sh = 0.f;
        unsigned v8[8], mx = 0u, mn = 0xFFFFFFFFu;
        #pragma unroll
        for (int j = 0; j < 4; j++) { float x = rad[tid + 256 * j]; sr += x * x; }
        #pragma unroll
        for (int j = 0; j < 8; j++) {
            float x = his[tid + 256 * j];
            sh += x * x;
            unsigned o = f2ord(x);
            v8[j] = o; mx = max(mx, o); mn = min(mn, o);
        }
        #pragma unroll
        for (int o = 16; o > 0; o >>= 1) {
            sr += __shfl_xor_sync(FULL, sr, o);
            sh += __shfl_xor_sync(FULL, sh, o);
        }
        mx = __reduce_max_sync(FULL, mx);
        mn = __reduce_min_sync(FULL, mn);
        if (lane == 0) { sm.p.red[wid] = sr; sm.p.red[8 + wid] = sh; sm.p.mm[wid] = mx; sm.p.mm[8 + wid] = mn; }
        __syncthreads();

        #pragma unroll
        for (int j = 0; j < 8; j++) atomicAdd(&sm.p.hist[v8[j] >> 21], 1u);

        if (tid == 0) {
            float a = 0.f, c2 = 0.f;
            unsigned MX = 0u, MN = 0xFFFFFFFFu;
            #pragma unroll
            for (int w = 0; w < 8; w++) {
                a += sm.p.red[w]; c2 += sm.p.red[8 + w];
                MX = max(MX, sm.p.mm[w]); MN = min(MN, sm.p.mm[8 + w]);
            }
            sm.p.scal[0] = 1.f / fmaxf(sqrtf(a),  1e-12f);
            sm.p.scal[1] = 1.f / fmaxf(sqrtf(c2), 1e-12f);
            sm.p.mm[0] = MX; sm.p.mm[8] = MN;
        }
        __syncthreads();

        if (wid == 0) {
            int bin = (int)(sm.p.mm[0] >> 21);
            unsigned cum = 0;
            while (true) {
                int ib = bin - lane;
                unsigned c = (ib >= 0) ? sm.p.hist[ib] : 0u;
                unsigned p = c;
                #pragma unroll
                for (int o = 1; o < 32; o <<= 1) {
                    unsigned t = __shfl_up_sync(FULL, p, o);
                    if (lane >= o) p += t;
                }
                unsigned ball = __ballot_sync(FULL, cum + p >= 16u);
                if (ball) {
                    int l = __ffs(ball) - 1;
                    unsigned pl = __shfl_sync(FULL, p, l);
                    unsigned cl = __shfl_sync(FULL, c, l);
                    if (lane == 0) { sm.p.bnd[0] = bin - l; sm.p.bnd[1] = (int)(cum + pl - cl); }
                    break;
                }
                cum += __shfl_sync(FULL, p, 31);
                bin -= 32;
            }
        } else if (wid == 1) {
            int bin = (int)(sm.p.mm[8] >> 21);
            unsigned cum = 0;
            while (true) {
                int ib = bin + lane;
                unsigned c = (ib < 2048) ? sm.p.hist[ib] : 0u;
                unsigned p = c;
                #pragma unroll
                for (int o = 1; o < 32; o <<= 1) {
                    unsigned t = __shfl_up_sync(FULL, p, o);
                    if (lane >= o) p += t;
                }
                unsigned ball = __ballot_sync(FULL, cum + p >= 16u);
                if (ball) {
                    int l = __ffs(ball) - 1;
                    unsigned pl = __shfl_sync(FULL, p, l);
                    unsigned cl = __shfl_sync(FULL, c, l);
                    if (lane == 0) { sm.p.bnd[2] = bin + l; sm.p.bnd[3] = (int)(cum + pl - cl); }
                    break;
                }
                cum += __shfl_sync(FULL, p, 31);
                bin += 32;
            }
        }
        __syncthreads();

        const int Btop = sm.p.bnd[0];
        const int Bbot = sm.p.bnd[2];

        float sA = 0.f, sB = 0.f;
        #pragma unroll
        for (int j = 0; j < 8; j++) {
            unsigned o = v8[j];
            int bn = (int)(o >> 21);
            if (bn > Btop)       sA += ord2f(o);
            else if (bn == Btop) { unsigned p = atomicAdd(&sm.p.cnt[0], 1u); sm.p.candT[p] = o; }
            if (bn < Bbot)       sB += ord2f(o);
            else if (bn == Bbot) { unsigned p = atomicAdd(&sm.p.cnt[1], 1u); sm.p.candB[p] = o; }
        }
        #pragma unroll
        for (int o = 16; o > 0; o >>= 1) {
            sA += __shfl_xor_sync(FULL, sA, o);
            sB += __shfl_xor_sync(FULL, sB, o);
        }
        if (lane == 0) { sm.p.sum[wid] = sA; sm.p.sum[8 + wid] = sB; }
        __syncthreads();

        if (wid == 0) {
            float sum = 0.f;
            #pragma unroll
            for (int w = 0; w < 8; w++) sum += sm.p.sum[w];
            const int m = 16 - sm.p.bnd[1];
            const int cnt = (int)sm.p.cnt[0];
            for (int pass = 0; pass < m; pass++) {
                unsigned best = 0u;
                for (int i = lane; i < cnt; i += 32) best = max(best, sm.p.candT[i]);
                unsigned wm = __reduce_max_sync(FULL, best);
                sum += ord2f(wm);
                int idx = -1;
                for (int i = lane; i < cnt; i += 32)
                    if (sm.p.candT[i] == wm) { idx = i; break; }
                unsigned ball = __ballot_sync(FULL, idx >= 0);
                if (lane == (int)__ffs(ball) - 1) sm.p.candT[idx] = 0u;
            }
            if (lane == 0) sm.p.scal[2] = sum;
        } else if (wid == 1) {
            float sum = 0.f;
            #pragma unroll
            for (int w = 0; w < 8; w++) sum += sm.p.sum[8 + w];
            const int m = 16 - sm.p.bnd[3];
            const int cnt = (int)sm.p.cnt[1];
            for (int pass = 0; pass < m; pass++) {
                unsigned best = 0xFFFFFFFFu;
                for (int i = lane; i < cnt; i += 32) best = min(best, sm.p.candB[i]);
                unsigned wm = __reduce_min_sync(FULL, best);
                sum += ord2f(wm);
                int idx = -1;
                for (int i = lane; i < cnt; i += 32)
                    if (sm.p.candB[i] == wm) { idx = i; break; }
                unsigned ball = __ballot_sync(FULL, idx >= 0);
                if (lane == (int)__ffs(ball) - 1) sm.p.candB[idx] = 0xFFFFFFFFu;
            }
            if (lane == 0) sm.p.scal[3] = sum;
        }
        __syncthreads();

        if (tid == 0) {
            float flag = ((rad_mask[b] != 0) && (histo_mask[b] != 0)) ? 0.f : 1.f;
            float Tp = sm.p.scal[1] * sm.p.scal[2] * (1.f / 16.f);
            float Tn = sm.p.scal[1] * sm.p.scal[3] * (1.f / 16.f);
            g_scal[b] = make_float4(sm.p.scal[0], Tp, Tn, flag);
            __threadfence();
            atomicAdd(&g_prep, 1u);   // publish scalars
            atomicAdd(&g_all, 1u);    // arrive
        }
        return;
    }

    // ============ GEMM: 64 c x 128 k per block, 2 chunks of 64 k ============
    const int gb    = blockIdx.x - 32;
    const int c0    = (gb & 15) * 64;
    const int split = gb >> 4;           // 0..15
    const int k0    = split * 128;

    {
        const float4* W4 = (const float4*)W;
        const int kq  = tid & 15;
        const int cl  = tid >> 4;
        const int kq0 = k0 >> 2;
        float4 wv[2][4];
        #pragma unroll
        for (int ch = 0; ch < 2; ch++)
            #pragma unroll
            for (int j = 0; j < 4; j++)
                wv[ch][j] = W4[(size_t)(c0 + cl + 16 * j) * 512 + kq0 + 16 * ch + kq];

        const float4* R4 = (const float4*)f_rad;
        const int kb = (k0 & 1023) >> 2;
        float4 rv[2][2];
        #pragma unroll
        for (int ch = 0; ch < 2; ch++)
            #pragma unroll
            for (int j = 0; j < 2; j++) {
                int i = tid + 256 * j;
                rv[ch][j] = R4[(size_t)(i >> 4) * 256 + kb + 16 * ch + (i & 15)];
            }

        unsigned long long accp[8], accm[8];
        #pragma unroll
        for (int c = 0; c < 8; c++) { accp[c] = 0ull; accm[c] = 0ull; }
        const int cw = wid * 8;

        #pragma unroll
        for (int ch = 0; ch < 2; ch++) {
            if (ch == 1) __syncthreads();
            #pragma unroll
            for (int j = 0; j < 2; j++) {
                int i  = tid + 256 * j;
                int bb = i >> 4;
                float4 r = rv[ch][j], p, m;
                p.x = fmaxf(r.x, 0.f); m.x = fminf(r.x, 0.f);
                p.y = fmaxf(r.y, 0.f); m.y = fminf(r.y, 0.f);
                p.z = fmaxf(r.z, 0.f); m.z = fminf(r.z, 0.f);
                p.w = fmaxf(r.w, 0.f); m.w = fminf(r.w, 0.f);
                *(float4*)&sm.g.FsP[bb * 68 + 4 * (i & 15)] = p;
                *(float4*)&sm.g.FsM[bb * 68 + 4 * (i & 15)] = m;
            }
            #pragma unroll
            for (int j = 0; j < 4; j++)
                *(float4*)&sm.g.Ws[(cl + 16 * j) * 64 + 4 * kq] = wv[ch][j];
            __syncthreads();

            const ulonglong2* wrow = (const ulonglong2*)&sm.g.Ws[cw * 64];
            const ulonglong2* fp   = (const ulonglong2*)&sm.g.FsP[lane * 68];
            const ulonglong2* fm   = (const ulonglong2*)&sm.g.FsM[lane * 68];
            #pragma unroll
            for (int ki = 0; ki < 16; ki++) {
                ulonglong2 fpv = fp[ki];
                ulonglong2 fmv = fm[ki];
                #pragma unroll
                for (int c = 0; c < 8; c++) {
                    ulonglong2 w = wrow[c * 16 + ki];
                    accp[c] = ffma2(w.x, fpv.x, accp[c]);
                    accp[c] = ffma2(w.y, fpv.y, accp[c]);
                    accm[c] = ffma2(w.x, fmv.x, accm[c]);
                    accm[c] = ffma2(w.y, fmv.y, accm[c]);
                }
            }
        }

        // ---- wait for prep scalars (prep never waits -> deadlock-free)
        if (tid == 0) {
            volatile unsigned* pf = &g_prep;
            while (*pf < 32u) { __nanosleep(128); }
        }
        __syncthreads();
        __threadfence();   // acquire g_scal

        // ---- fold coefficients (lane = b), store ONE combined partial
        float4 sc = g_scal[lane];
        const float cp = sc.x * sc.y;
        const float cn = sc.x * sc.z;
        const float coefP = (split < 8) ? cp : -cn;
        const float coefM = (split < 8) ? cn : -cp;

        float oc[8];
        #pragma unroll
        for (int c = 0; c < 8; c++) {
            float pv = __uint_as_float((unsigned)(accp[c] & 0xffffffffull))
                     + __uint_as_float((unsigned)(accp[c] >> 32));
            float mv = __uint_as_float((unsigned)(accm[c] & 0xffffffffull))
                     + __uint_as_float((unsigned)(accm[c] >> 32));
            oc[c] = coefP * pv + coefM * mv;
        }
        float* dst = &g_comb[(((size_t)split) * 32 + lane) * 1024 + c0 + cw];
        *(float4*)(dst + 0) = make_float4(oc[0], oc[1], oc[2], oc[3]);
        *(float4*)(dst + 4) = make_float4(oc[4], oc[5], oc[6], oc[7]);
    }

    // ---- global barrier (all 288 co-resident at (256,2) => safe) ----
    __threadfence();
    __syncthreads();
    if (tid == 0) {
        atomicAdd(&g_all, 1u);
        volatile unsigned* pa = &g_all;
        while (*pa < 288u) { __nanosleep(64); }
    }
    __syncthreads();
    __threadfence();   // acquire all combined partials

    // ================= REDUCE (L2-hot, 2MB): rb keys (b, c-chunk) =============
    {
        const int rb  = blockIdx.x - 32;     // 0..255
        const int b   = rb >> 3;
        const int cc  = rb & 7;
        const int col = tid & 31;
        const int grp = tid >> 5;            // 8 grps x 2 splits each

        const float4* P4 = (const float4*)g_comb;
        const size_t base = (size_t)b * 256 + cc * 32 + col;

        float4 v0 = P4[base + (size_t)(grp * 2 + 0) * 8192];
        float4 v1 = P4[base + (size_t)(grp * 2 + 1) * 8192];
        __syncthreads();   // GEMM smem dead; reuse as tree
        sm.r.s_p[grp][col] = make_float4(v0.x + v1.x, v0.y + v1.y,
                                         v0.z + v1.z, v0.w + v1.w);
        __syncthreads();

        if (grp == 0) {
            float4 t = sm.r.s_p[0][col];
            #pragma unroll
            for (int g = 1; g < 8; g++) {
                float4 u = sm.r.s_p[g][col];
                t.x += u.x; t.y += u.y; t.z += u.z; t.w += u.w;
            }
            const int bq = cc * 32 + col;
            float4 bs = ((const float4*)bias)[bq];
            float4 tk = ((const float4*)token)[bq];
            const float flag = g_scal[b].w;
            float4 o;
            o.x = t.x + bs.x + flag * tk.x;
            o.y = t.y + bs.y + flag * tk.y;
            o.z = t.z + bs.z + flag * tk.z;
            o.w = t.w + bs.w + flag * tk.w;
            ((float4*)out)[base] = o;
        }
    }

    // ---- self-reset (last reducer; all spinners already released) ----
    __syncthreads();
    if (tid == 0) {
        __threadfence();
        unsigned d = atomicAdd(&g_rdone, 1u);
        if (d == 255u) {
            g_all   = 0u;
            g_prep  = 0u;
            g_rdone = 0u;
            __threadfence();
        }
    }
}

extern "C" void kernel_launch(void* const* d_in, const int* in_sizes, int n_in,
                              void* d_out, int out_size) {
    const float* f_rad      = (const float*)d_in[0];
    const float* f_histo    = (const float*)d_in[1];
    const int*   rad_mask   = (const int*)  d_in[2];
    const int*   histo_mask = (const int*)  d_in[3];
    const float* W          = (const float*)d_in[4];
    const float* bias       = (const float*)d_in[5];
    const float* token      = (const float*)d_in[6];
    float* out = (float*)d_out;

    fused_kernel<<<288, 256>>>(f_rad, f_histo, rad_mask, histo_mask,
                               W, bias, token, out);
}

// round 15
// speedup vs baseline: 1.2424x; 1.2424x over previous
#include <cuda_runtime.h>
#include <cstdint>

#define FULL 0xFFFFFFFFu

// PDL primitives (sm_90+): early-trigger dependent launch + dependent wait.
#define PDL_TRIGGER() asm volatile("griddepcontrol.launch_dependents;" ::: "memory")
#define PDL_WAIT()    asm volatile("griddepcontrol.wait;" ::: "memory")

// Static scratch (no allocations):
__device__ float4 g_scal[32];                 // per-b: {inv_r, Tp, Tn, flag}
__device__ float  g_part[2 * 16 * 32 * 1024]; // [arr(p/m)][split][b][c], 4MB

// Order-preserving float <-> uint mapping (monotone for non-NaN).
__device__ __forceinline__ unsigned f2ord(float f) {
    unsigned b = __float_as_uint(f);
    return (b & 0x80000000u) ? ~b : (b | 0x80000000u);
}
__device__ __forceinline__ float ord2f(unsigned u) {
    unsigned b = (u & 0x80000000u) ? (u ^ 0x80000000u) : ~u;
    return __uint_as_float(b);
}

// Packed fp32x2 FMA (Blackwell FFMA2).
__device__ __forceinline__ unsigned long long ffma2(
    unsigned long long a, unsigned long long b, unsigned long long c) {
    unsigned long long d;
    asm("fma.rn.f32x2 %0, %1, %2, %3;" : "=l"(d) : "l"(a), "l"(b), "l"(c));
    return d;
}

union SmemU {
    struct {
        unsigned hist[2048];
        unsigned candT[2048];
        unsigned candB[2048];
        float    red[16];
        unsigned mm[16];
        int      bnd[4];
        unsigned cnt[2];
        float    sum[16];
        float    scal[4];
    } p;
    struct {
        float Ws[64 * 64];      // [c][k] 16KB
        float FsP[32 * 68];     // max(rad,0), pitch 68
        float FsM[32 * 68];     // min(rad,0)
    } g;
};

// ---------------------------------------------------------------------------
// Kernel 1 (R11 structure, unchanged math), grid = 288:
//   blocks 0..31   : prep -> g_scal (+ PDL trigger after publish)
//   blocks 32..287 : GEMM partials 64c x 128k (2 chunks of 64k), store two
//                    raw arrays (Pp/Pm), PDL trigger after stores, exit.
// ---------------------------------------------------------------------------
__global__ void __launch_bounds__(256) fused_kernel(
    const float* __restrict__ f_rad,    // [32,1024]
    const float* __restrict__ f_histo,  // [32,2048]
    const int*   __restrict__ rad_mask, // [32]
    const int*   __restrict__ histo_mask,
    const float* __restrict__ W)        // [1024,2048]
{
    __shared__ __align__(16) SmemU sm;

    const int tid  = threadIdx.x;
    const int lane = tid & 31;
    const int wid  = tid >> 5;

    if (blockIdx.x < 32) {
        // ======================= PREP (proven) =======================
        const int b = blockIdx.x;
        const float* rad = f_rad   + b * 1024;
        const float* his = f_histo + b * 2048;

        #pragma unroll
        for (int j = 0; j < 8; j++) sm.p.hist[tid + 256 * j] = 0;
        if (tid < 2) sm.p.cnt[tid] = 0;

        float sr = 0.f, sh = 0.f;
        unsigned v8[8], mx = 0u, mn = 0xFFFFFFFFu;
        #pragma unroll
        for (int j = 0; j < 4; j++) { float x = rad[tid + 256 * j]; sr += x * x; }
        #pragma unroll
        for (int j = 0; j < 8; j++) {
            float x = his[tid + 256 * j];
            sh += x * x;
            unsigned o = f2ord(x);
            v8[j] = o; mx = max(mx, o); mn = min(mn, o);
        }
        #pragma unroll
        for (int o = 16; o > 0; o >>= 1) {
            sr += __shfl_xor_sync(FULL, sr, o);
            sh += __shfl_xor_sync(FULL, sh, o);
        }
        mx = __reduce_max_sync(FULL, mx);
        mn = __reduce_min_sync(FULL, mn);
        if (lane == 0) { sm.p.red[wid] = sr; sm.p.red[8 + wid] = sh; sm.p.mm[wid] = mx; sm.p.mm[8 + wid] = mn; }
        __syncthreads();

        #pragma unroll
        for (int j = 0; j < 8; j++) atomicAdd(&sm.p.hist[v8[j] >> 21], 1u);

        if (tid == 0) {
            float a = 0.f, c2 = 0.f;
            unsigned MX = 0u, MN = 0xFFFFFFFFu;
            #pragma unroll
            for (int w = 0; w < 8; w++) {
                a += sm.p.red[w]; c2 += sm.p.red[8 + w];
                MX = max(MX, sm.p.mm[w]); MN = min(MN, sm.p.mm[8 + w]);
            }
            sm.p.scal[0] = 1.f / fmaxf(sqrtf(a),  1e-12f);
            sm.p.scal[1] = 1.f / fmaxf(sqrtf(c2), 1e-12f);
            sm.p.mm[0] = MX; sm.p.mm[8] = MN;
        }
        __syncthreads();

        if (wid == 0) {
            int bin = (int)(sm.p.mm[0] >> 21);
            unsigned cum = 0;
            while (true) {
                int ib = bin - lane;
                unsigned c = (ib >= 0) ? sm.p.hist[ib] : 0u;
                unsigned p = c;
                #pragma unroll
                for (int o = 1; o < 32; o <<= 1) {
                    unsigned t = __shfl_up_sync(FULL, p, o);
                    if (lane >= o) p += t;
                }
                unsigned ball = __ballot_sync(FULL, cum + p >= 16u);
                if (ball) {
                    int l = __ffs(ball) - 1;
                    unsigned pl = __shfl_sync(FULL, p, l);
                    unsigned cl = __shfl_sync(FULL, c, l);
                    if (lane == 0) { sm.p.bnd[0] = bin - l; sm.p.bnd[1] = (int)(cum + pl - cl); }
                    break;
                }
                cum += __shfl_sync(FULL, p, 31);
                bin -= 32;
            }
        } else if (wid == 1) {
            int bin = (int)(sm.p.mm[8] >> 21);
            unsigned cum = 0;
            while (true) {
                int ib = bin + lane;
                unsigned c = (ib < 2048) ? sm.p.hist[ib] : 0u;
                unsigned p = c;
                #pragma unroll
                for (int o = 1; o < 32; o <<= 1) {
                    unsigned t = __shfl_up_sync(FULL, p, o);
                    if (lane >= o) p += t;
                }
                unsigned ball = __ballot_sync(FULL, cum + p >= 16u);
                if (ball) {
                    int l = __ffs(ball) - 1;
                    unsigned pl = __shfl_sync(FULL, p, l);
                    unsigned cl = __shfl_sync(FULL, c, l);
                    if (lane == 0) { sm.p.bnd[2] = bin + l; sm.p.bnd[3] = (int)(cum + pl - cl); }
                    break;
                }
                cum += __shfl_sync(FULL, p, 31);
                bin += 32;
            }
        }
        __syncthreads();

        const int Btop = sm.p.bnd[0];
        const int Bbot = sm.p.bnd[2];

        float sA = 0.f, sB = 0.f;
        #pragma unroll
        for (int j = 0; j < 8; j++) {
            unsigned o = v8[j];
            int bn = (int)(o >> 21);
            if (bn > Btop)       sA += ord2f(o);
            else if (bn == Btop) { unsigned p = atomicAdd(&sm.p.cnt[0], 1u); sm.p.candT[p] = o; }
            if (bn < Bbot)       sB += ord2f(o);
            else if (bn == Bbot) { unsigned p = atomicAdd(&sm.p.cnt[1], 1u); sm.p.candB[p] = o; }
        }
        #pragma unroll
        for (int o = 16; o > 0; o >>= 1) {
            sA += __shfl_xor_sync(FULL, sA, o);
            sB += __shfl_xor_sync(FULL, sB, o);
        }
        if (lane == 0) { sm.p.sum[wid] = sA; sm.p.sum[8 + wid] = sB; }
        __syncthreads();

        if (wid == 0) {
            float sum = 0.f;
            #pragma unroll
            for (int w = 0; w < 8; w++) sum += sm.p.sum[w];
            const int m = 16 - sm.p.bnd[1];
            const int cnt = (int)sm.p.cnt[0];
            for (int pass = 0; pass < m; pass++) {
                unsigned best = 0u;
                for (int i = lane; i < cnt; i += 32) best = max(best, sm.p.candT[i]);
                unsigned wm = __reduce_max_sync(FULL, best);
                sum += ord2f(wm);
                int idx = -1;
                for (int i = lane; i < cnt; i += 32)
                    if (sm.p.candT[i] == wm) { idx = i; break; }
                unsigned ball = __ballot_sync(FULL, idx >= 0);
                if (lane == (int)__ffs(ball) - 1) sm.p.candT[idx] = 0u;
            }
            if (lane == 0) sm.p.scal[2] = sum;
        } else if (wid == 1) {
            float sum = 0.f;
            #pragma unroll
            for (int w = 0; w < 8; w++) sum += sm.p.sum[8 + w];
            const int m = 16 - sm.p.bnd[3];
            const int cnt = (int)sm.p.cnt[1];
            for (int pass = 0; pass < m; pass++) {
                unsigned best = 0xFFFFFFFFu;
                for (int i = lane; i < cnt; i += 32) best = min(best, sm.p.candB[i]);
                unsigned wm = __reduce_min_sync(FULL, best);
                sum += ord2f(wm);
                int idx = -1;
                for (int i = lane; i < cnt; i += 32)
                    if (sm.p.candB[i] == wm) { idx = i; break; }
                unsigned ball = __ballot_sync(FULL, idx >= 0);
                if (lane == (int)__ffs(ball) - 1) sm.p.candB[idx] = 0xFFFFFFFFu;
            }
            if (lane == 0) sm.p.scal[3] = sum;
        }
        __syncthreads();

        if (tid == 0) {
            float flag = ((rad_mask[b] != 0) && (histo_mask[b] != 0)) ? 0.f : 1.f;
            float Tp = sm.p.scal[1] * sm.p.scal[2] * (1.f / 16.f);
            float Tn = sm.p.scal[1] * sm.p.scal[3] * (1.f / 16.f);
            g_scal[b] = make_float4(sm.p.scal[0], Tp, Tn, flag);
            __threadfence();
            PDL_TRIGGER();     // outputs published; allow dependent launch
        }
    } else {
        // ============ GEMM: 64 c x 128 k per block, 2 chunks of 64 k ============
        const int gb    = blockIdx.x - 32;
        const int c0    = (gb & 15) * 64;
        const int split = gb >> 4;           // 0..15
        const int k0    = split * 128;

        const float4* W4 = (const float4*)W;
        const int kq  = tid & 15;
        const int cl  = tid >> 4;
        const int kq0 = k0 >> 2;
        float4 wv[2][4];
        #pragma unroll
        for (int ch = 0; ch < 2; ch++)
            #pragma unroll
            for (int j = 0; j < 4; j++)
                wv[ch][j] = W4[(size_t)(c0 + cl + 16 * j) * 512 + kq0 + 16 * ch + kq];

        const float4* R4 = (const float4*)f_rad;
        const int kb = (k0 & 1023) >> 2;
        float4 rv[2][2];
        #pragma unroll
        for (int ch = 0; ch < 2; ch++)
            #pragma unroll
            for (int j = 0; j < 2; j++) {
                int i = tid + 256 * j;
                rv[ch][j] = R4[(size_t)(i >> 4) * 256 + kb + 16 * ch + (i & 15)];
            }

        unsigned long long accp[8], accm[8];
        #pragma unroll
        for (int c = 0; c < 8; c++) { accp[c] = 0ull; accm[c] = 0ull; }
        const int cw = wid * 8;

        #pragma unroll
        for (int ch = 0; ch < 2; ch++) {
            if (ch == 1) __syncthreads();
            #pragma unroll
            for (int j = 0; j < 2; j++) {
                int i  = tid + 256 * j;
                int bb = i >> 4;
                float4 r = rv[ch][j], p, m;
                p.x = fmaxf(r.x, 0.f); m.x = fminf(r.x, 0.f);
                p.y = fmaxf(r.y, 0.f); m.y = fminf(r.y, 0.f);
                p.z = fmaxf(r.z, 0.f); m.z = fminf(r.z, 0.f);
                p.w = fmaxf(r.w, 0.f); m.w = fminf(r.w, 0.f);
                *(float4*)&sm.g.FsP[bb * 68 + 4 * (i & 15)] = p;
                *(float4*)&sm.g.FsM[bb * 68 + 4 * (i & 15)] = m;
            }
            #pragma unroll
            for (int j = 0; j < 4; j++)
                *(float4*)&sm.g.Ws[(cl + 16 * j) * 64 + 4 * kq] = wv[ch][j];
            __syncthreads();

            const ulonglong2* wrow = (const ulonglong2*)&sm.g.Ws[cw * 64];
            const ulonglong2* fp   = (const ulonglong2*)&sm.g.FsP[lane * 68];
            const ulonglong2* fm   = (const ulonglong2*)&sm.g.FsM[lane * 68];
            #pragma unroll
            for (int ki = 0; ki < 16; ki++) {
                ulonglong2 fpv = fp[ki];
                ulonglong2 fmv = fm[ki];
                #pragma unroll
                for (int c = 0; c < 8; c++) {
                    ulonglong2 w = wrow[c * 16 + ki];
                    accp[c] = ffma2(w.x, fpv.x, accp[c]);
                    accp[c] = ffma2(w.y, fpv.y, accp[c]);
                    accm[c] = ffma2(w.x, fmv.x, accm[c]);
                    accm[c] = ffma2(w.y, fmv.y, accm[c]);
                }
            }
        }

        float op[8], om[8];
        #pragma unroll
        for (int c = 0; c < 8; c++) {
            op[c] = __uint_as_float((unsigned)(accp[c] & 0xffffffffull))
                  + __uint_as_float((unsigned)(accp[c] >> 32));
            om[c] = __uint_as_float((unsigned)(accm[c] & 0xffffffffull))
                  + __uint_as_float((unsigned)(accm[c] >> 32));
        }
        float* dp = &g_part[(((size_t)0 * 16 + split) * 32 + lane) * 1024 + c0 + cw];
        float* dm = &g_part[(((size_t)1 * 16 + split) * 32 + lane) * 1024 + c0 + cw];
        *(float4*)(dp + 0) = make_float4(op[0], op[1], op[2], op[3]);
        *(float4*)(dp + 4) = make_float4(op[4], op[5], op[6], op[7]);
        *(float4*)(dm + 0) = make_float4(om[0], om[1], om[2], om[3]);
        *(float4*)(dm + 4) = make_float4(om[4], om[5], om[6], om[7]);

        __threadfence();
        __syncthreads();
        if (tid == 0) PDL_TRIGGER();   // partials published
    }
}

// ---------------------------------------------------------------------------
// Reduce (R11 v3 layout) with PDL: independent prologue (indices + bias/token
// loads) BEFORE griddepcontrol.wait; dependent loads (g_scal, g_part) after.
// 256 blocks (32 b x 8 c-chunks of 128), 256 threads; 8 grps x 4 pairs each.
// ---------------------------------------------------------------------------
__global__ void __launch_bounds__(256) reduce_kernel(
    const float* __restrict__ bias,   // [1024]
    const float* __restrict__ token,  // [1024]
    float* __restrict__ out)          // [32,1024]
{
    const int b   = blockIdx.x >> 3;
    const int cc  = blockIdx.x & 7;
    const int col = threadIdx.x & 31;
    const int grp = threadIdx.x >> 5;

    __shared__ float4 s_p[8][32];

    const size_t base = (size_t)b * 256 + cc * 32 + col;
    const int bq = cc * 32 + col;

    // --- independent prologue: issue bias/token loads before the wait
    float4 bs = make_float4(0, 0, 0, 0), tk = make_float4(0, 0, 0, 0);
    if (grp == 0) {
        bs = __ldg(&((const float4*)bias)[bq]);
        tk = __ldg(&((const float4*)token)[bq]);
    }

    PDL_WAIT();   // block until fused_kernel's outputs are visible

    float4 sc = g_scal[b];
    const float cp = sc.x * sc.y;   // inv_r * Tp
    const float cn = sc.x * sc.z;   // inv_r * Tn

    const float4* P4 = (const float4*)g_part;
    float4 v[4];
    #pragma unroll
    for (int j = 0; j < 4; j++)
        v[j] = P4[base + (size_t)(grp * 4 + j) * 8192];

    float4 acc = make_float4(0, 0, 0, 0);
    #pragma unroll
    for (int j = 0; j < 4; j++) {
        int p   = grp * 4 + j;
        int s   = p & 15;
        int arr = p >> 4;
        bool pos = (s < 8);
        float mag  = ((arr == 0) == pos) ? cp : cn;
        float coef = pos ? mag : -mag;
        acc.x += coef * v[j].x;
        acc.y += coef * v[j].y;
        acc.z += coef * v[j].z;
        acc.w += coef * v[j].w;
    }
    s_p[grp][col] = acc;
    __syncthreads();

    if (grp == 0) {
        float4 t = s_p[0][col];
        #pragma unroll
        for (int g = 1; g < 8; g++) {
            float4 u = s_p[g][col];
            t.x += u.x; t.y += u.y; t.z += u.z; t.w += u.w;
        }
        const float flag = sc.w;
        float4 o;
        o.x = t.x + bs.x + flag * tk.x;
        o.y = t.y + bs.y + flag * tk.y;
        o.z = t.z + bs.z + flag * tk.z;
        o.w = t.w + bs.w + flag * tk.w;
        ((float4*)out)[base] = o;
    }
}

extern "C" void kernel_launch(void* const* d_in, const int* in_sizes, int n_in,
                              void* d_out, int out_size) {
    const float* f_rad      = (const float*)d_in[0];
    const float* f_histo    = (const float*)d_in[1];
    const int*   rad_mask   = (const int*)  d_in[2];
    const int*   histo_mask = (const int*)  d_in[3];
    const float* W          = (const float*)d_in[4];
    const float* bias       = (const float*)d_in[5];
    const float* token      = (const float*)d_in[6];
    float* out = (float*)d_out;

    fused_kernel<<<288, 256>>>(f_rad, f_histo, rad_mask, histo_mask, W);

    // Launch reduce with Programmatic Stream Serialization (PDL):
    // it may begin while fused_kernel is still resident; its dependent
    // section is gated by griddepcontrol.wait.
    cudaLaunchConfig_t cfg = {};
    cfg.gridDim  = dim3(256);
    cfg.blockDim = dim3(256);
    cfg.dynamicSmemBytes = 0;
    cfg.stream = 0;
    cudaLaunchAttribute attrs[1];
    attrs[0].id = cudaLaunchAttributeProgrammaticStreamSerialization;
    attrs[0].val.programmaticStreamSerializationAllowed = 1;
    cfg.attrs = attrs;
    cfg.numAttrs = 1;
    cudaLaunchKernelEx(&cfg, reduce_kernel, bias, token, (float*)out);
}